// round 1
// baseline (speedup 1.0000x reference)
#include <cuda_runtime.h>
#include <math.h>

// ---------------- problem constants ----------------
#define Bn      2
#define Tn      16384
#define Ln      64
#define HOPn    256
#define INCH    101
#define INNERC  128
#define CONDC   81
#define KHC     64
#define COUTC   256
#define LAYERSn 5
#define KCHn    491520          // 5*128*256*3
#define BCHn    1280            // 256*5
#define RPL     98304           // rows per layer = 128*256*3

// ---------------- scratch (static device memory; no allocation) ----------------
__device__ float g_h [Bn*INNERC*Tn];              // running residual h  (16.8 MB)
__device__ float g_x1[Bn*INNERC*Tn];              // ping
__device__ float g_y1[Bn*INNERC*Tn];              // pong
__device__ float g_hc[2*Bn*KHC*Ln];               // predictor hidden   (64 KB)
__device__ float g_bs[2*Bn*BCHn*Ln];              // predicted biases   (2.6 MB)
__device__ float g_W [(size_t)Bn*Ln*RPL];         // per-layer weights  (50.3 MB)

// =====================================================================
// 1) fc: h[b,o,t] = fc_W[o,:] . x[b,:,t] + fc_b[o]   (101 -> 128)
//    grid (T/32, B), 128 threads (one per o), 32 t per CTA
// =====================================================================
__global__ void fc_kernel(const float* __restrict__ x,
                          const float* __restrict__ W,
                          const float* __restrict__ bias,
                          float* __restrict__ out)
{
    __shared__ float sx[INCH*32];        // x tile [101][32]
    __shared__ float sW[128*33];         // W chunk [128][<=32] padded
    const int b  = blockIdx.y;
    const int t0 = blockIdx.x * 32;
    const int tid = threadIdx.x;

    for (int p = tid; p < INCH*32; p += 128) {
        int c = p >> 5, j = p & 31;
        sx[p] = x[((size_t)(b*INCH + c))*Tn + t0 + j];
    }
    float acc[32];
    float bv = bias[tid];
#pragma unroll
    for (int j = 0; j < 32; j++) acc[j] = bv;

    for (int c0 = 0; c0 < INCH; c0 += 32) {
        int cmax = (INCH - c0) < 32 ? (INCH - c0) : 32;
        __syncthreads();
        for (int p = tid; p < 128*32; p += 128) {
            int o = p >> 5, cl = p & 31;
            if (cl < cmax) sW[o*33 + cl] = W[o*INCH + c0 + cl];
        }
        __syncthreads();
        for (int cl = 0; cl < cmax; cl++) {
            float w = sW[tid*33 + cl];
            const float* xr = &sx[(c0 + cl)*32];
#pragma unroll
            for (int j = 0; j < 32; j++) acc[j] += w * xr[j];
        }
    }
    float* o = &out[((size_t)(b*INNERC + tid))*Tn + t0];
#pragma unroll
    for (int j = 0; j < 32; j++) o[j] = acc[j];
}

// =====================================================================
// 2) kernel predictor conditioning net (tiny): 4 CTAs = (n,b)
//    h1 = lrelu(conv5(c));  h = h1 + r2W@lrelu(r1W@h1 + r1b) + r2b
//    writes g_hc and the predicted biases g_bs
// =====================================================================
__global__ void predictor_kernel(const float* __restrict__ cond,
                                 const float* __restrict__ iW, const float* __restrict__ ib,
                                 const float* __restrict__ r1W, const float* __restrict__ r1b,
                                 const float* __restrict__ r2W, const float* __restrict__ r2b,
                                 const float* __restrict__ bW,  const float* __restrict__ bb,
                                 float* __restrict__ hc_out, float* __restrict__ bias_out)
{
    __shared__ float bufc[CONDC*Ln];   // cond, later reused for h2
    __shared__ float bufh[KHC*Ln];     // h1, overwritten in place by h3
    const int nb = blockIdx.x;         // n*2 + b
    const int n  = nb >> 1;
    const int b  = nb & 1;
    const int tid = threadIdx.x;

    for (int p = tid; p < CONDC*Ln; p += 256) bufc[p] = cond[b*CONDC*Ln + p];
    __syncthreads();

    // conv5 + lrelu -> bufh (h1)
    for (int idx = tid; idx < KHC*Ln; idx += 256) {
        int kh = idx >> 6, l = idx & 63;
        float a = ib[n*KHC + kh];
        const float* wrow = &iW[(size_t)(n*KHC + kh)*CONDC*5];
        for (int cc = 0; cc < CONDC; cc++) {
#pragma unroll
            for (int k = 0; k < 5; k++) {
                int ll = l + k - 2;
                if (ll >= 0 && ll < Ln) a += bufc[cc*Ln + ll] * wrow[cc*5 + k];
            }
        }
        bufh[idx] = a >= 0.f ? a : 0.1f*a;
    }
    __syncthreads();

    // h2 = lrelu(r1W @ h1) -> bufc (cond no longer needed)
    for (int idx = tid; idx < KHC*Ln; idx += 256) {
        int o = idx >> 6, l = idx & 63;
        float a = r1b[n*KHC + o];
        const float* wr = &r1W[(size_t)(n*KHC + o)*KHC];
        for (int i = 0; i < KHC; i++) a += wr[i] * bufh[i*Ln + l];
        bufc[idx] = a >= 0.f ? a : 0.1f*a;
    }
    __syncthreads();

    // h3 = h1 + r2W @ h2  (in-place into bufh: each idx reads only bufh[idx])
    for (int idx = tid; idx < KHC*Ln; idx += 256) {
        int o = idx >> 6, l = idx & 63;
        float a = r2b[n*KHC + o];
        const float* wr = &r2W[(size_t)(n*KHC + o)*KHC];
        for (int i = 0; i < KHC; i++) a += wr[i] * bufc[i*Ln + l];
        bufh[idx] = bufh[idx] + a;
    }
    __syncthreads();

    for (int idx = tid; idx < KHC*Ln; idx += 256) hc_out[nb*KHC*Ln + idx] = bufh[idx];

    // biases: g_bs[nb][j][l] = bW[n,j,:] . hc[:,l] + bb[n,j]
    for (int idx = tid; idx < BCHn*Ln; idx += 256) {
        int j = idx >> 6, l = idx & 63;
        float a = bb[n*BCHn + j];
        const float* wr = &bW[(size_t)(n*BCHn + j)*KHC];
        for (int i = 0; i < KHC; i++) a += wr[i] * bufh[i*Ln + l];
        bias_out[(size_t)nb*BCHn*Ln + idx] = a;
    }
}

// =====================================================================
// 3) weight GEMM per (block n, layer):
//    g_W[(b*64+l)*RPL + row] = kern_W[n, layer*RPL+row, :] . hc[n,b,:,l] + kern_b
//    CTA: 128 rows x 128 cols, 256 threads, thread tile 8x8, K tiled by 32
// =====================================================================
__global__ void wgemm_kernel(const float* __restrict__ kW,
                             const float* __restrict__ kb,
                             const float* __restrict__ hc,
                             float* __restrict__ gW,
                             int n, int layer)
{
    __shared__ float sA[128*33];
    __shared__ float sB[32*128];
    const int tid = threadIdx.x;
    const int R0  = blockIdx.x * 128;
    const size_t base = (size_t)n*KCHn*64 + (size_t)(layer*RPL + R0)*64;

    const int rg = tid >> 4;       // 0..15
    const int cg = tid & 15;       // 0..15
    const int r0 = rg * 8;

    float acc[8][8];
#pragma unroll
    for (int rr = 0; rr < 8; rr++) {
        float bb = kb[(size_t)n*KCHn + layer*RPL + R0 + r0 + rr];
#pragma unroll
        for (int cc = 0; cc < 8; cc++) acc[rr][cc] = bb;
    }

    for (int k0 = 0; k0 < 64; k0 += 32) {
        for (int p = tid; p < 128*32; p += 256) {
            int r = p >> 5, kk = p & 31;
            sA[r*33 + kk] = kW[base + (size_t)r*64 + k0 + kk];
        }
        for (int p = tid; p < 32*128; p += 256) {
            int kk = p >> 7, col = p & 127;
            int b = col >> 6, l = col & 63;
            sB[p] = hc[((n*2 + b)*KHC + (k0 + kk))*Ln + l];
        }
        __syncthreads();
        for (int kk = 0; kk < 32; kk++) {
            float a[8], bf[8];
#pragma unroll
            for (int rr = 0; rr < 8; rr++) a[rr] = sA[(r0 + rr)*33 + kk];
#pragma unroll
            for (int cc = 0; cc < 8; cc++) bf[cc] = sB[kk*128 + cg + 16*cc];
#pragma unroll
            for (int rr = 0; rr < 8; rr++)
#pragma unroll
                for (int cc = 0; cc < 8; cc++) acc[rr][cc] += a[rr]*bf[cc];
        }
        __syncthreads();
    }

#pragma unroll
    for (int cc = 0; cc < 8; cc++) {
        int col = cg + 16*cc;
        float* op = &gW[(size_t)col*RPL + R0 + r0];
#pragma unroll
        for (int rr = 0; rr < 8; rr += 4) {
            float4 v = make_float4(acc[rr][cc], acc[rr+1][cc], acc[rr+2][cc], acc[rr+3][cc]);
            *(float4*)(op + rr) = v;
        }
    }
}

// =====================================================================
// 4) LVC layer: CTA = (half, l, b), 512 threads.
//    y[o,s] = bias[o,l] + sum_{i,k} x[i, t+(k-1)d] * W[b,l,i,o,k]
//    out[o<128] = sigmoid(y[o]) * tanh(y[o+128])
//    GEMM view: 256o x 128s x (128i*3k), thread tile 8o x 8s (strided s)
// =====================================================================
template<int D>
__global__ void __launch_bounds__(512,1)
lvc_kernel(const float* __restrict__ xin, float* __restrict__ xout,
           const float* __restrict__ gW, const float* __restrict__ gbias,
           int n, int layer, int accflag)
{
    extern __shared__ float smem[];
    float* xs    = smem;                  // [128][161]
    float* sW    = smem + 128*161;        // [48][256]
    float* sbias = sW + 48*256;           // [256]

    const int hf  = blockIdx.x;           // 0/1: which 128-sample half
    const int l   = blockIdx.y;
    const int b   = blockIdx.z;
    const int tid = threadIdx.x;
    const int tx  = tid & 15;             // s group
    const int ty  = tid >> 4;             // o group (0..31)
    const int olo = ty * 4;

    const int t_base = l*HOPn + hf*128;
    const int win = 128 + 2*D;

    // load x window (zero pad at sequence edges)
    for (int p = tid; p < 128*win; p += 512) {
        int i = p / win;
        int j = p - i*win;
        int t = t_base - D + j;
        float v = (t >= 0 && t < Tn) ? xin[((size_t)(b*INNERC + i))*Tn + t] : 0.f;
        xs[i*161 + j] = v;
    }
    if (tid < 256)
        sbias[tid] = gbias[(size_t)(((n*2 + b)*BCHn) + layer*COUTC + tid)*Ln + l];
    __syncthreads();

    float acc[8][8];
#pragma unroll
    for (int r = 0; r < 4; r++) {
        float blo = sbias[olo + r], bhi = sbias[olo + r + 128];
#pragma unroll
        for (int j = 0; j < 8; j++) { acc[r][j] = blo; acc[r+4][j] = bhi; }
    }

    const size_t wbase = (size_t)(b*Ln + l)*RPL;

    for (int ii0 = 0; ii0 < 128; ii0 += 16) {
        // stage W chunk: 16 input channels x 256 out x 3 taps
        const float4* src = (const float4*)(gW + wbase + (size_t)ii0*768);
        for (int p4 = tid; p4 < 3072; p4 += 512) {
            float4 v = src[p4];
            int p = p4 * 4;
#pragma unroll
            for (int e = 0; e < 4; e++) {
                int pe = p + e;
                int k = pe % 3;
                int rest = pe / 3;
                int o  = rest & 255;
                int il = rest >> 8;
                sW[(il*3 + k)*256 + o] = ((const float*)&v)[e];
            }
        }
        __syncthreads();

        for (int il = 0; il < 16; il++) {
            const float* xrow = xs + (ii0 + il)*161;
#pragma unroll
            for (int k = 0; k < 3; k++) {
                const float* wrow = sW + (il*3 + k)*256;
                float4 wlo = *(const float4*)(wrow + olo);
                float4 whi = *(const float4*)(wrow + olo + 128);
                const int off = tx + k*D;
                float xv[8];
#pragma unroll
                for (int j = 0; j < 8; j++) xv[j] = xrow[off + 16*j];
#pragma unroll
                for (int j = 0; j < 8; j++) {
                    acc[0][j] += wlo.x*xv[j];  acc[1][j] += wlo.y*xv[j];
                    acc[2][j] += wlo.z*xv[j];  acc[3][j] += wlo.w*xv[j];
                    acc[4][j] += whi.x*xv[j];  acc[5][j] += whi.y*xv[j];
                    acc[6][j] += whi.z*xv[j];  acc[7][j] += whi.w*xv[j];
                }
            }
        }
        __syncthreads();
    }

    // gate + write
#pragma unroll
    for (int r = 0; r < 4; r++) {
        int o = olo + r;
        float* orow = xout + ((size_t)(b*INNERC + o))*Tn + t_base;
#pragma unroll
        for (int j = 0; j < 8; j++) {
            int s = tx + 16*j;
            float sg = 1.f / (1.f + __expf(-acc[r][j]));
            float th = tanhf(acc[r+4][j]);
            float v = sg * th;
            if (accflag) v += orow[s];
            orow[s] = v;
        }
    }
}

// =====================================================================
// 5) final: out = lc2_W . relu(lc1_W @ relu(h) + lc1_b) + lc2_b
//    grid (T/32, B), 128 threads
// =====================================================================
__global__ void final_kernel(const float* __restrict__ h,
                             const float* __restrict__ W1, const float* __restrict__ b1,
                             const float* __restrict__ W2, const float* __restrict__ b2,
                             float* __restrict__ out)
{
    __shared__ float bufA[64*129];   // W1 chunk (transposed), later h2 [128][33]
    __shared__ float bufB[64*32];    // relu(h) chunk
    const int b  = blockIdx.y;
    const int t0 = blockIdx.x * 32;
    const int tid = threadIdx.x;

    float acc[32];
    float bv = b1[tid];
#pragma unroll
    for (int j = 0; j < 32; j++) acc[j] = bv;

    for (int c0 = 0; c0 < 128; c0 += 64) {
        __syncthreads();
        for (int p = tid; p < 128*64; p += 128) {
            int o = p >> 6, cl = p & 63;
            bufA[cl*129 + o] = W1[o*128 + c0 + cl];
        }
        for (int p = tid; p < 64*32; p += 128) {
            int cl = p >> 5, j = p & 31;
            float v = h[((size_t)(b*INNERC + c0 + cl))*Tn + t0 + j];
            bufB[p] = v > 0.f ? v : 0.f;
        }
        __syncthreads();
        for (int cl = 0; cl < 64; cl++) {
            float w = bufA[cl*129 + tid];
            const float* xr = &bufB[cl*32];
#pragma unroll
            for (int j = 0; j < 32; j++) acc[j] += w * xr[j];
        }
    }
    __syncthreads();
#pragma unroll
    for (int j = 0; j < 32; j++) bufA[tid*33 + j] = acc[j] > 0.f ? acc[j] : 0.f;
    __syncthreads();
    if (tid < 32) {
        float s = b2[0];
        for (int o = 0; o < 128; o++) s += W2[o] * bufA[o*33 + tid];
        out[(size_t)b*Tn + t0 + tid] = s;
    }
}

// =====================================================================
// launcher
// =====================================================================
#define LVC_SMEM ((128*161 + 48*256 + 256) * (int)sizeof(float))

extern "C" void kernel_launch(void* const* d_in, const int* in_sizes, int n_in,
                              void* d_out, int out_size)
{
    (void)in_sizes; (void)n_in; (void)out_size;
    const float* x      = (const float*)d_in[0];
    const float* cnd    = (const float*)d_in[1];
    const float* fc_W   = (const float*)d_in[2];
    const float* fc_b   = (const float*)d_in[3];
    const float* inp_W  = (const float*)d_in[4];
    const float* inp_b  = (const float*)d_in[5];
    const float* res1_W = (const float*)d_in[6];
    const float* res1_b = (const float*)d_in[7];
    const float* res2_W = (const float*)d_in[8];
    const float* res2_b = (const float*)d_in[9];
    const float* kern_W = (const float*)d_in[10];
    const float* kern_b = (const float*)d_in[11];
    const float* bc_W   = (const float*)d_in[12];
    const float* bc_b   = (const float*)d_in[13];
    const float* lc1_W  = (const float*)d_in[14];
    const float* lc1_b  = (const float*)d_in[15];
    const float* lc2_W  = (const float*)d_in[16];
    const float* lc2_b  = (const float*)d_in[17];
    float* out = (float*)d_out;

    float *h, *xb, *yb, *hc, *bs, *W;
    cudaGetSymbolAddress((void**)&h,  g_h);
    cudaGetSymbolAddress((void**)&xb, g_x1);
    cudaGetSymbolAddress((void**)&yb, g_y1);
    cudaGetSymbolAddress((void**)&hc, g_hc);
    cudaGetSymbolAddress((void**)&bs, g_bs);
    cudaGetSymbolAddress((void**)&W,  g_W);

    cudaFuncSetAttribute(lvc_kernel<1>,  cudaFuncAttributeMaxDynamicSharedMemorySize, LVC_SMEM);
    cudaFuncSetAttribute(lvc_kernel<2>,  cudaFuncAttributeMaxDynamicSharedMemorySize, LVC_SMEM);
    cudaFuncSetAttribute(lvc_kernel<4>,  cudaFuncAttributeMaxDynamicSharedMemorySize, LVC_SMEM);
    cudaFuncSetAttribute(lvc_kernel<8>,  cudaFuncAttributeMaxDynamicSharedMemorySize, LVC_SMEM);
    cudaFuncSetAttribute(lvc_kernel<16>, cudaFuncAttributeMaxDynamicSharedMemorySize, LVC_SMEM);

    fc_kernel<<<dim3(Tn/32, Bn), 128>>>(x, fc_W, fc_b, h);
    predictor_kernel<<<4, 256>>>(cnd, inp_W, inp_b, res1_W, res1_b,
                                 res2_W, res2_b, bc_W, bc_b, hc, bs);

    for (int n = 0; n < 2; n++) {
        const float* cur = h;
        for (int i = 0; i < 5; i++) {
            wgemm_kernel<<<RPL/128, 256>>>(kern_W, kern_b, hc, W, n, i);
            float* outp = (i == 4) ? h : ((i & 1) ? yb : xb);
            int accfl = (i == 4 && n == 1) ? 1 : 0;
            dim3 g(2, Ln, Bn);
            switch (i) {
                case 0: lvc_kernel<1> <<<g, 512, LVC_SMEM>>>(cur, outp, W, bs, n, i, accfl); break;
                case 1: lvc_kernel<2> <<<g, 512, LVC_SMEM>>>(cur, outp, W, bs, n, i, accfl); break;
                case 2: lvc_kernel<4> <<<g, 512, LVC_SMEM>>>(cur, outp, W, bs, n, i, accfl); break;
                case 3: lvc_kernel<8> <<<g, 512, LVC_SMEM>>>(cur, outp, W, bs, n, i, accfl); break;
                case 4: lvc_kernel<16><<<g, 512, LVC_SMEM>>>(cur, outp, W, bs, n, i, accfl); break;
            }
            cur = outp;
        }
    }

    final_kernel<<<dim3(Tn/32, Bn), 128>>>(h, lc1_W, lc1_b, lc2_W, lc2_b, out);
}